// round 8
// baseline (speedup 1.0000x reference)
#include <cuda_runtime.h>

// Windowed local attention, k=7, H=W=256, C=32, fp32.
// Thread = (pixel-pair vertical, channel half): 2 px x 16 ch.
// 8x7 union window: 56 LDS serve 98 MACs per channel. Scores combined
// across channel halves with shfl_xor(16). Tile 16x8, 128 thr, halo 22x14.

#define H_IMG 256
#define W_IMG 256
#define C 32
#define K 7
#define PAD 3
#define TX 16
#define TY 8
#define HW 22              // TX + K - 1
#define HH 14              // TY + K - 1
#define NPOS (HW * HH)     // 308
#define CS 309             // channel stride (odd)
#define NTHREADS 128
#define SMEM_BYTES (C * CS * 4)   // 39552

// Stage one tensor's halo: [c][pos] channel-major, zero-padded OOB.
__device__ __forceinline__ void stage_halo(float* __restrict__ buf,
                                           const float* __restrict__ src,
                                           int bx, int by, int tid) {
    for (int idx = tid; idx < NPOS * (C / 4); idx += NTHREADS) {
        int g  = idx & 7;
        int s  = idx >> 3;
        int wp = s % HW;
        int hp = s / HW;
        int gw = bx * TX - PAD + wp;
        int gh = by * TY - PAD + hp;
        float4 r = make_float4(0.f, 0.f, 0.f, 0.f);
        if (gw >= 0 && gw < W_IMG && gh >= 0 && gh < H_IMG) {
            r = *reinterpret_cast<const float4*>(src + ((gh << 8) + gw) * C + (g << 2));
        }
        int c0 = g << 2;
        buf[(c0 + 0) * CS + s] = r.x;
        buf[(c0 + 1) * CS + s] = r.y;
        buf[(c0 + 2) * CS + s] = r.z;
        buf[(c0 + 3) * CS + s] = r.w;
    }
}

__global__ __launch_bounds__(NTHREADS, 3)
void local_attn_kernel(const float* __restrict__ main_in,
                       const float* __restrict__ ref_in,
                       const float* __restrict__ val_in,
                       float* __restrict__ out) {
    extern __shared__ float smem[];
    float* buf = smem;

    const int tid  = threadIdx.x;
    const int bx   = blockIdx.x, by = blockIdx.y;
    const int lane = tid & 31;
    const int warp = tid >> 5;              // owns tile rows 2w, 2w+1
    const int px   = lane & 15;
    const int half = lane >> 4;             // channel half
    const int ch0  = half << 4;             // 0 or 16
    const int h0   = warp << 1;
    const int s0   = h0 * HW + px;          // window origin (pixel 0)

    const int gy0   = by * TY + h0;
    const int gpix0 = ((gy0 << 8) + bx * TX + px) * C;
    const int gpix1 = gpix0 + W_IMG * C;

    // ---- Stage ref halo ----
    stage_halo(buf, ref_in, bx, by, tid);
    __syncthreads();

    // ---- Pass 1: partial scores over this thread's 16 channels ----
    float sc0[K * K], sc1[K * K];
    #pragma unroll
    for (int p = 0; p < K * K; p++) { sc0[p] = 0.f; sc1[p] = 0.f; }

    #pragma unroll
    for (int cc = 0; cc < 2; cc++) {        // 8-channel sub-chunks
        float q0[8], q1[8];
        #pragma unroll
        for (int i = 0; i < 2; i++) {
            float4 a = *reinterpret_cast<const float4*>(main_in + gpix0 + ch0 + cc * 8 + 4 * i);
            float4 b = *reinterpret_cast<const float4*>(main_in + gpix1 + ch0 + cc * 8 + 4 * i);
            q0[4 * i + 0] = a.x; q0[4 * i + 1] = a.y; q0[4 * i + 2] = a.z; q0[4 * i + 3] = a.w;
            q1[4 * i + 0] = b.x; q1[4 * i + 1] = b.y; q1[4 * i + 2] = b.z; q1[4 * i + 3] = b.w;
        }
        #pragma unroll
        for (int c = 0; c < 8; c++) {
            const float* base = buf + (ch0 + cc * 8 + c) * CS + s0;
            #pragma unroll
            for (int dh = 0; dh < K + 1; dh++) {
                #pragma unroll
                for (int dw = 0; dw < K; dw++) {
                    float v = base[dh * HW + dw];
                    if (dh < K)  sc0[dh * K + dw]       = fmaf(v, q0[c], sc0[dh * K + dw]);
                    if (dh >= 1) sc1[(dh - 1) * K + dw] = fmaf(v, q1[c], sc1[(dh - 1) * K + dw]);
                }
            }
        }
    }

    // ---- Combine channel halves (partner lane 16 apart) ----
    #pragma unroll
    for (int p = 0; p < K * K; p++) {
        sc0[p] += __shfl_xor_sync(0xffffffffu, sc0[p], 16);
        sc1[p] += __shfl_xor_sync(0xffffffffu, sc1[p], 16);
    }

    // ---- Softmax (OOB positions carry score 0, included) ----
    {
        float mx0 = sc0[0], mx1 = sc1[0];
        #pragma unroll
        for (int p = 1; p < K * K; p++) { mx0 = fmaxf(mx0, sc0[p]); mx1 = fmaxf(mx1, sc1[p]); }
        float sm0 = 0.f, sm1 = 0.f;
        #pragma unroll
        for (int p = 0; p < K * K; p++) {
            sc0[p] = __expf(sc0[p] - mx0); sm0 += sc0[p];
            sc1[p] = __expf(sc1[p] - mx1); sm1 += sc1[p];
        }
        float i0 = 1.f / sm0, i1 = 1.f / sm1;
        #pragma unroll
        for (int p = 0; p < K * K; p++) { sc0[p] *= i0; sc1[p] *= i1; }
    }

    // ---- Stage val halo (reuse buffer) ----
    __syncthreads();
    stage_halo(buf, val_in, bx, by, tid);
    __syncthreads();

    // ---- Pass 2: this thread's 16 channels for both pixels ----
    #pragma unroll
    for (int g = 0; g < 4; g++) {           // 4-channel groups
        float a0[4] = {0.f, 0.f, 0.f, 0.f};
        float a1[4] = {0.f, 0.f, 0.f, 0.f};
        #pragma unroll
        for (int c = 0; c < 4; c++) {
            const float* base = buf + (ch0 + (g << 2) + c) * CS + s0;
            #pragma unroll
            for (int dh = 0; dh < K + 1; dh++) {
                #pragma unroll
                for (int dw = 0; dw < K; dw++) {
                    float v = base[dh * HW + dw];
                    if (dh < K)  a0[c] = fmaf(v, sc0[dh * K + dw], a0[c]);
                    if (dh >= 1) a1[c] = fmaf(v, sc1[(dh - 1) * K + dw], a1[c]);
                }
            }
        }
        *reinterpret_cast<float4*>(out + gpix0 + ch0 + (g << 2)) =
            make_float4(a0[0], a0[1], a0[2], a0[3]);
        *reinterpret_cast<float4*>(out + gpix1 + ch0 + (g << 2)) =
            make_float4(a1[0], a1[1], a1[2], a1[3]);
    }
}

extern "C" void kernel_launch(void* const* d_in, const int* in_sizes, int n_in,
                              void* d_out, int out_size) {
    const float* main_in = (const float*)d_in[0];
    const float* ref_in  = (const float*)d_in[1];
    const float* val_in  = (const float*)d_in[2];
    float* out = (float*)d_out;

    cudaFuncSetAttribute(local_attn_kernel,
                         cudaFuncAttributeMaxDynamicSharedMemorySize, SMEM_BYTES);

    dim3 grid(W_IMG / TX, H_IMG / TY);
    local_attn_kernel<<<grid, NTHREADS, SMEM_BYTES>>>(main_in, ref_in, val_in, out);
}

// round 9
// speedup vs baseline: 1.1050x; 1.1050x over previous
#include <cuda_runtime.h>

// Windowed local attention, k=7, H=W=256, C=32, fp32.
// Thread = (vertical pixel-pair, window-row half). Lane l and l+16 share a
// pixel pair; half A owns union-window rows 0-3, half B rows 4-7.
// 56 score accumulators/thread (vs 98) -> ~95 regs -> 2048 warps total.
// Halo row stride 44: half-warp smem offset 176 = 16 mod 32 -> every LDS
// is one conflict-free 128B wavefront. Same crossbar bytes as best kernel.

#define H_IMG 256
#define W_IMG 256
#define C 32
#define K 7
#define PAD 3
#define TX 32
#define TY 8
#define HW 38               // used cols: TX + K - 1
#define HWS 44              // padded row stride (4*44 % 32 == 16)
#define HH 14               // TY + K - 1
#define CHST (HH * HWS)     // 616 floats per channel
#define NTHREADS 256
#define SMEM_BYTES (C * CHST * 4)   // 78848

// Stage one tensor's halo: [c][row*HWS + col], zero-padded OOB.
__device__ __forceinline__ void stage_halo(float* __restrict__ buf,
                                           const float* __restrict__ src,
                                           int bx, int by, int tid) {
    for (int p = tid; p < HW * HH; p += NTHREADS) {
        int hp = p / HW;
        int wp = p - hp * HW;
        int gw = bx * TX - PAD + wp;
        int gh = by * TY - PAD + hp;
        bool ok = (gw >= 0) && (gw < W_IMG) && (gh >= 0) && (gh < H_IMG);
        int sa = hp * HWS + wp;
        int ga = ((gh << 8) + gw) * C;
        #pragma unroll
        for (int g = 0; g < 8; g++) {
            float4 r = make_float4(0.f, 0.f, 0.f, 0.f);
            if (ok) r = *reinterpret_cast<const float4*>(src + ga + (g << 2));
            float* d = buf + (g << 2) * CHST + sa;
            d[0 * CHST] = r.x;
            d[1 * CHST] = r.y;
            d[2 * CHST] = r.z;
            d[3 * CHST] = r.w;
        }
    }
}

__global__ __launch_bounds__(NTHREADS, 2)
void local_attn_kernel(const float* __restrict__ main_in,
                       const float* __restrict__ ref_in,
                       const float* __restrict__ val_in,
                       float* __restrict__ out) {
    extern __shared__ float smem[];

    const int tid  = threadIdx.x;
    const int bx   = blockIdx.x, by = blockIdx.y;
    const int warp = tid >> 5;            // 0..7
    const int lane = tid & 31;
    const int half = lane >> 4;           // 0: union rows 0-3, 1: rows 4-7
    const int pr   = warp >> 1;           // pair-row 0..3 (tile rows 2pr,2pr+1)
    const int px   = ((warp & 1) << 4) + (lane & 15);

    // This thread's 4 halo rows start at rb; smem pos offset:
    const int sbase = (2 * pr + 4 * half) * HWS + px;

    const int gy0   = by * TY + 2 * pr;
    const int gpix0 = ((gy0 << 8) + bx * TX + px) * C;   // pixel0 (row 2pr)
    const int gpix1 = gpix0 + W_IMG * C;                 // pixel1 (row 2pr+1)
    const int gprim = half ? gpix1 : gpix0;              // primary pixel
    const int gseco = half ? gpix0 : gpix1;              // secondary pixel

    // ---- Stage ref halo ----
    stage_halo(smem, ref_in, bx, by, tid);
    __syncthreads();

    // ---- Pass 1: prim/seco partial scores over 4 local rows x 7 cols ----
    // prim[r*7+dw]: primary pixel's score contribution at local row r.
    // seco[r*7+dw]: secondary pixel's (A: valid r>=1, B: valid r<=2).
    float prim[28], seco[28];
    #pragma unroll
    for (int i = 0; i < 28; i++) { prim[i] = 0.f; seco[i] = 0.f; }

    #pragma unroll
    for (int cc = 0; cc < 4; cc++) {                 // 8-channel chunks
        float qp[8], qs[8];
        #pragma unroll
        for (int i = 0; i < 2; i++) {
            float4 a = *reinterpret_cast<const float4*>(main_in + gprim + cc * 8 + 4 * i);
            float4 b = *reinterpret_cast<const float4*>(main_in + gseco + cc * 8 + 4 * i);
            qp[4 * i + 0] = a.x; qp[4 * i + 1] = a.y; qp[4 * i + 2] = a.z; qp[4 * i + 3] = a.w;
            qs[4 * i + 0] = b.x; qs[4 * i + 1] = b.y; qs[4 * i + 2] = b.z; qs[4 * i + 3] = b.w;
        }
        #pragma unroll
        for (int c = 0; c < 8; c++) {
            const float* base = smem + (cc * 8 + c) * CHST + sbase;
            #pragma unroll
            for (int r = 0; r < 4; r++) {
                #pragma unroll
                for (int dw = 0; dw < K; dw++) {
                    float v = base[r * HWS + dw];
                    prim[r * 7 + dw] = fmaf(v, qp[c], prim[r * 7 + dw]);
                    seco[r * 7 + dw] = fmaf(v, qs[c], seco[r * 7 + dw]);
                }
            }
        }
    }

    // ---- Split softmax: combine pair lanes via shfl_xor(16) ----
    // (OOB halo positions carry score 0 and are included, matching reference.)
    float lmP = -1e30f, lmS = -1e30f;
    #pragma unroll
    for (int i = 0; i < 28; i++) lmP = fmaxf(lmP, prim[i]);
    #pragma unroll
    for (int r = 0; r < 4; r++) {
        bool valid = half ? (r <= 2) : (r >= 1);
        #pragma unroll
        for (int dw = 0; dw < K; dw++) {
            float s = valid ? seco[r * 7 + dw] : -1e30f;
            lmS = fmaxf(lmS, s);
        }
    }
    float gmP = fmaxf(lmP, __shfl_xor_sync(0xffffffffu, lmS, 16));
    float gmS = fmaxf(lmS, __shfl_xor_sync(0xffffffffu, lmP, 16));

    float lsP = 0.f, lsS = 0.f;
    #pragma unroll
    for (int i = 0; i < 28; i++) {
        prim[i] = __expf(prim[i] - gmP);
        lsP += prim[i];
    }
    #pragma unroll
    for (int r = 0; r < 4; r++) {
        bool valid = half ? (r <= 2) : (r >= 1);
        #pragma unroll
        for (int dw = 0; dw < K; dw++) {
            float e = valid ? __expf(seco[r * 7 + dw] - gmS) : 0.f;
            seco[r * 7 + dw] = e;
            lsS += e;
        }
    }
    float gsP = lsP + __shfl_xor_sync(0xffffffffu, lsS, 16);
    float gsS = lsS + __shfl_xor_sync(0xffffffffu, lsP, 16);
    float ivP = 1.f / gsP, ivS = 1.f / gsS;
    #pragma unroll
    for (int i = 0; i < 28; i++) { prim[i] *= ivP; seco[i] *= ivS; }
    // garbage seco rows now hold weight 0 -> pass 2 is branch-free.

    // ---- Stage val halo (reuse buffer) ----
    __syncthreads();
    stage_halo(smem, val_in, bx, by, tid);
    __syncthreads();

    // ---- Pass 2: partial outputs; combine with partner lane; store ----
    #pragma unroll
    for (int g = 0; g < 8; g++) {
        float oP[4] = {0.f, 0.f, 0.f, 0.f};
        float oS[4] = {0.f, 0.f, 0.f, 0.f};
        #pragma unroll
        for (int c = 0; c < 4; c++) {
            const float* base = smem + ((g << 2) + c) * CHST + sbase;
            #pragma unroll
            for (int r = 0; r < 4; r++) {
                #pragma unroll
                for (int dw = 0; dw < K; dw++) {
                    float v = base[r * HWS + dw];
                    oP[c] = fmaf(v, prim[r * 7 + dw], oP[c]);
                    oS[c] = fmaf(v, seco[r * 7 + dw], oS[c]);
                }
            }
        }
        // partner's oS is the other half of my primary pixel
        float f0 = oP[0] + __shfl_xor_sync(0xffffffffu, oS[0], 16);
        float f1 = oP[1] + __shfl_xor_sync(0xffffffffu, oS[1], 16);
        float f2 = oP[2] + __shfl_xor_sync(0xffffffffu, oS[2], 16);
        float f3 = oP[3] + __shfl_xor_sync(0xffffffffu, oS[3], 16);
        *reinterpret_cast<float4*>(out + gprim + (g << 2)) =
            make_float4(f0, f1, f2, f3);
    }
}

extern "C" void kernel_launch(void* const* d_in, const int* in_sizes, int n_in,
                              void* d_out, int out_size) {
    const float* main_in = (const float*)d_in[0];
    const float* ref_in  = (const float*)d_in[1];
    const float* val_in  = (const float*)d_in[2];
    float* out = (float*)d_out;

    cudaFuncSetAttribute(local_attn_kernel,
                         cudaFuncAttributeMaxDynamicSharedMemorySize, SMEM_BYTES);

    dim3 grid(W_IMG / TX, H_IMG / TY);
    local_attn_kernel<<<grid, NTHREADS, SMEM_BYTES>>>(main_in, ref_in, val_in, out);
}